// round 3
// baseline (speedup 1.0000x reference)
#include <cuda_runtime.h>
#include <cuda_bf16.h>
#include <math.h>
#include <stdint.h>

#define BB   32
#define SS   512
#define INF  512
#define HH   1024
#define NG   4096
#define NCTA 128

// Scratch (static device globals — allocation-free per harness rules)
__device__ float g_gxT[(size_t)SS * NG * BB];   // x-part gates, [s][n][b]
__device__ float g_out0[(size_t)BB * SS * HH];  // layer0 outputs [b][s][h]
__device__ float g_hG[2][HH * BB];              // ping-pong h, layout [k4][b][4]
__device__ unsigned g_barCnt;
__device__ unsigned g_barRel;

// bf16 hi/lo split buffers
__device__ __nv_bfloat16 g_Ah[(size_t)16384 * 1024];
__device__ __nv_bfloat16 g_Al[(size_t)16384 * 1024];
__device__ __nv_bfloat16 g_Wh[(size_t)4096 * 1024];
__device__ __nv_bfloat16 g_Wl[(size_t)4096 * 1024];

// ---------------------------------------------------------------------------
__global__ void init_kernel() {
    int idx = blockIdx.x * blockDim.x + threadIdx.x;
    if (idx < HH * BB) g_hG[0][idx] = 0.0f;
    if (idx == 0) { g_barCnt = 0u; g_barRel = 0u; }
}

// ---------------------------------------------------------------------------
// Split fp32 matrix (rows x cols, row stride srcld) into bf16 hi + lo.
// use_out0: src = g_out0 instead of the passed pointer.
__global__ void split_mat(const float* __restrict__ src, int srcld, int cols,
                          int total, __nv_bfloat16* __restrict__ hi,
                          __nv_bfloat16* __restrict__ lo, int use_out0)
{
    const float* s = use_out0 ? g_out0 : src;
    int idx = blockIdx.x * blockDim.x + threadIdx.x;
    if (idx >= total) return;
    int r = idx / cols, c = idx - r * cols;
    float v = s[(size_t)r * srcld + c];
    __nv_bfloat16 h = __float2bfloat16(v);
    hi[idx] = h;
    lo[idx] = __float2bfloat16(v - __bfloat162float(h));
}

// ---------------------------------------------------------------------------
__device__ __forceinline__ void mma16816(float* d, const uint32_t* a,
                                         const uint32_t* b)
{
    asm volatile(
        "mma.sync.aligned.m16n8k16.row.col.f32.bf16.bf16.f32 "
        "{%0,%1,%2,%3}, {%4,%5,%6,%7}, {%8,%9}, {%0,%1,%2,%3};\n"
        : "+f"(d[0]), "+f"(d[1]), "+f"(d[2]), "+f"(d[3])
        : "r"(a[0]), "r"(a[1]), "r"(a[2]), "r"(a[3]), "r"(b[0]), "r"(b[1]));
}

// Tensor-core x-projection GEMM, 3-term bf16 split, fp32 accumulate.
// C[m][n] = sum_k A[m][k]*W[n][k] + bias[n], scattered to g_gxT[s][n][b].
// A: [16384 x K] (hi/lo), W: [4096 x K] (hi/lo). CTA tile 128x128, 8 warps.
__global__ __launch_bounds__(256, 2) void gemm_x_bf16(
    const __nv_bfloat16* __restrict__ Ah, const __nv_bfloat16* __restrict__ Al,
    const __nv_bfloat16* __restrict__ Bh, const __nv_bfloat16* __restrict__ Bl,
    const float* __restrict__ bias, int K)
{
    __shared__ uint32_t smA_h[128 * 20];
    __shared__ uint32_t smA_l[128 * 20];
    __shared__ uint32_t smB_h[128 * 20];
    __shared__ uint32_t smB_l[128 * 20];

    const int tid  = threadIdx.x;
    const int n0   = blockIdx.x * 128;
    const int m0   = blockIdx.y * 128;
    const int wid  = tid >> 5, lane = tid & 31;
    const int wm   = (wid >> 2) * 64;   // warp M offset (0/64)
    const int wn   = (wid & 3) * 32;    // warp N offset
    const int g    = lane >> 2, t = lane & 3;

    float acc[4][4][4];
#pragma unroll
    for (int mt = 0; mt < 4; mt++)
#pragma unroll
        for (int nt = 0; nt < 4; nt++)
#pragma unroll
            for (int i = 0; i < 4; i++) acc[mt][nt][i] = 0.0f;

    for (int k0 = 0; k0 < K; k0 += 32) {
        __syncthreads();
#pragma unroll
        for (int i = 0; i < 4; i++) {
            int q = i * 256 + tid;          // 0..1023
            int r = q >> 3, c = q & 7;      // row, uint2 col (8B = 4 bf16)
            size_t offA = (size_t)(m0 + r) * K + k0;
            size_t offB = (size_t)(n0 + r) * K + k0;
            ((uint2*)&smA_h[r * 20])[c] = ((const uint2*)(Ah + offA))[c];
            ((uint2*)&smA_l[r * 20])[c] = ((const uint2*)(Al + offA))[c];
            ((uint2*)&smB_h[r * 20])[c] = ((const uint2*)(Bh + offB))[c];
            ((uint2*)&smB_l[r * 20])[c] = ((const uint2*)(Bl + offB))[c];
        }
        __syncthreads();

#pragma unroll
        for (int kk = 0; kk < 2; kk++) {
            const int kb = kk * 8;
            uint32_t ah[4][4], al[4][4];
#pragma unroll
            for (int mt = 0; mt < 4; mt++) {
                int r0 = wm + mt * 16;
                ah[mt][0] = smA_h[(r0 + g)     * 20 + kb + t];
                ah[mt][1] = smA_h[(r0 + g + 8) * 20 + kb + t];
                ah[mt][2] = smA_h[(r0 + g)     * 20 + kb + t + 4];
                ah[mt][3] = smA_h[(r0 + g + 8) * 20 + kb + t + 4];
                al[mt][0] = smA_l[(r0 + g)     * 20 + kb + t];
                al[mt][1] = smA_l[(r0 + g + 8) * 20 + kb + t];
                al[mt][2] = smA_l[(r0 + g)     * 20 + kb + t + 4];
                al[mt][3] = smA_l[(r0 + g + 8) * 20 + kb + t + 4];
            }
#pragma unroll
            for (int nt = 0; nt < 4; nt++) {
                int c0 = wn + nt * 8;
                uint32_t bh[2], bl[2];
                bh[0] = smB_h[(c0 + g) * 20 + kb + t];
                bh[1] = smB_h[(c0 + g) * 20 + kb + t + 4];
                bl[0] = smB_l[(c0 + g) * 20 + kb + t];
                bl[1] = smB_l[(c0 + g) * 20 + kb + t + 4];
#pragma unroll
                for (int mt = 0; mt < 4; mt++) {
                    mma16816(acc[mt][nt], ah[mt], bh);
                    mma16816(acc[mt][nt], ah[mt], bl);
                    mma16816(acc[mt][nt], al[mt], bh);
                }
            }
        }
    }

    // epilogue: scatter to g_gxT[s][n][b] + bias
#pragma unroll
    for (int mt = 0; mt < 4; mt++) {
        int m1 = m0 + wm + mt * 16 + g;
        int m2 = m1 + 8;
        int b1 = m1 >> 9, s1 = m1 & 511;
        int b2 = m2 >> 9, s2 = m2 & 511;
#pragma unroll
        for (int nt = 0; nt < 4; nt++) {
            int n = n0 + wn + nt * 8 + 2 * t;
            float2 bv = *(const float2*)&bias[n];
            size_t o1 = ((size_t)s1 * NG + n) * BB + b1;
            size_t o2 = ((size_t)s2 * NG + n) * BB + b2;
            g_gxT[o1]      = acc[mt][nt][0] + bv.x;
            g_gxT[o1 + BB] = acc[mt][nt][1] + bv.y;
            g_gxT[o2]      = acc[mt][nt][2] + bv.x;
            g_gxT[o2 + BB] = acc[mt][nt][3] + bv.y;
        }
    }
}

// ---------------------------------------------------------------------------
// Persistent recurrent kernel (unchanged from R2, proven correct):
// 128 CTAs x 256 thr, 1 CTA/SM; Wh slice (128 KB) resident in smem.
#define SMEM_FLOATS (32768 + 8192 + 8448)

__global__ __launch_bounds__(256, 1) void lstm_layer(
    const float* __restrict__ W, int ldw, int Din,
    float* __restrict__ out, int layer)
{
    extern __shared__ float sm[];
    float* Wsm  = sm;
    float* hc   = sm + 32768;
    float* part = sm + 32768 + 8192;

    const int tid = threadIdx.x;
    const int cta = blockIdx.x;
    const int j0  = cta * 8;

    for (int i = 0; i < 32; i++) {
        int q  = i * 256 + tid;
        int l  = q & 31;
        int k4 = q >> 5;
        int gate = l >> 3, jj = l & 7;
        int n = gate * 1024 + j0 + jj;
        *(float4*)&Wsm[q * 4] =
            *(const float4*)(W + (size_t)n * ldw + Din + k4 * 4);
    }

    const int g  = tid >> 5;
    const int gt = tid & 31;
    const int b0 = (gt & 7) * 4;
    const int l0 = (gt >> 3) * 8;
    const int ub = tid & 31;
    const int uj = tid >> 5;
    const int ujglob = j0 + uj;

    float c_state = 0.0f;
    float h_last  = 0.0f;
    unsigned round = 0;

    __syncthreads();

    for (int t = 0; t < SS; t++) {
        round++;
        __syncthreads();
        if (tid == 0) {
            __threadfence();
            unsigned arrived = atomicAdd(&g_barCnt, 1u) + 1u;
            if (arrived == round * NCTA) {
                atomicExch(&g_barRel, round);
            } else {
                while (atomicAdd(&g_barRel, 0u) < round) { __nanosleep(128); }
            }
            __threadfence();
        }
        __syncthreads();

        const float* hin = g_hG[t & 1];

        float acc[4][8];
#pragma unroll
        for (int bb = 0; bb < 4; bb++)
#pragma unroll
            for (int nn = 0; nn < 8; nn++) acc[bb][nn] = 0.0f;

        for (int cch = 0; cch < 4; cch++) {
#pragma unroll
            for (int i = 0; i < 8; i++) {
                int q   = i * 256 + tid;
                int b   = q & 31;
                int idx = q >> 5;
                int gg  = idx >> 3, k4i = idx & 7;
                int k4  = gg * 32 + cch * 8 + k4i;
                *(float4*)&hc[q * 4] =
                    __ldcg((const float4*)&hin[(k4 * 32 + b) * 4]);
            }
            __syncthreads();
#pragma unroll
            for (int k4i = 0; k4i < 8; k4i++) {
                int k4    = g * 32 + cch * 8 + k4i;
                int hbase = (g * 8 + k4i) * 32;
                float4 hv[4];
#pragma unroll
                for (int bb = 0; bb < 4; bb++)
                    hv[bb] = *(float4*)&hc[(hbase + b0 + bb) * 4];
#pragma unroll
                for (int nn = 0; nn < 8; nn++) {
                    float4 wv = *(float4*)&Wsm[(k4 * 32 + l0 + nn) * 4];
#pragma unroll
                    for (int bb = 0; bb < 4; bb++)
                        acc[bb][nn] += hv[bb].x * wv.x + hv[bb].y * wv.y
                                     + hv[bb].z * wv.z + hv[bb].w * wv.w;
                }
            }
            __syncthreads();
        }

#pragma unroll
        for (int nn = 0; nn < 8; nn++)
#pragma unroll
            for (int bb = 0; bb < 4; bb++)
                part[(g * 32 + l0 + nn) * 33 + b0 + bb] = acc[bb][nn];
        __syncthreads();

        {
            size_t gbase = ((size_t)t * NG + ujglob) * BB + ub;
            float pi = g_gxT[gbase];
            float pf = g_gxT[gbase + (size_t)1024 * BB];
            float pg = g_gxT[gbase + (size_t)2048 * BB];
            float po = g_gxT[gbase + (size_t)3072 * BB];
#pragma unroll
            for (int gg = 0; gg < 8; gg++) {
                pi += part[(gg * 32 +  0 + uj) * 33 + ub];
                pf += part[(gg * 32 +  8 + uj) * 33 + ub];
                pg += part[(gg * 32 + 16 + uj) * 33 + ub];
                po += part[(gg * 32 + 24 + uj) * 33 + ub];
            }
            float gi = 1.0f / (1.0f + expf(-pi));
            float gf = 1.0f / (1.0f + expf(-pf));
            float gg_ = tanhf(pg);
            float go = 1.0f / (1.0f + expf(-po));
            c_state = gf * c_state + gi * gg_;
            float h = go * tanhf(c_state);
            h_last = h;
            __stcg(&g_hG[(t + 1) & 1][((ujglob >> 2) * 32 + ub) * 4 + (ujglob & 3)], h);
            if (layer == 0)
                g_out0[((size_t)ub * SS + t) * HH + ujglob] = h;
        }
    }

    out[32768 + layer * 32768 + ub * 1024 + ujglob] = h_last;
    out[98304 + layer * 32768 + ub * 1024 + ujglob] = c_state;
    if (layer == 1) out[ub * 1024 + ujglob] = h_last;
}

// ---------------------------------------------------------------------------
extern "C" void kernel_launch(void* const* d_in, const int* in_sizes, int n_in,
                              void* d_out, int out_size)
{
    const float* x  = (const float*)d_in[0];
    const float* W0 = (const float*)d_in[1];
    const float* b0 = (const float*)d_in[2];
    const float* W1 = (const float*)d_in[3];
    const float* b1 = (const float*)d_in[4];
    float* out = (float*)d_out;

    cudaFuncSetAttribute(lstm_layer,
        cudaFuncAttributeMaxDynamicSharedMemorySize, SMEM_FLOATS * 4);
    const int smem = SMEM_FLOATS * 4;

    __nv_bfloat16 *Ah, *Al, *Wh, *Wl;
    cudaGetSymbolAddress((void**)&Ah, g_Ah);
    cudaGetSymbolAddress((void**)&Al, g_Al);
    cudaGetSymbolAddress((void**)&Wh, g_Wh);
    cudaGetSymbolAddress((void**)&Wl, g_Wl);

    // ---- Layer 0 ----
    {
        int totA = 16384 * INF;               // x: [16384 x 512]
        split_mat<<<(totA + 255) / 256, 256>>>(x, INF, INF, totA, Ah, Al, 0);
        int totW = 4096 * INF;                // W0 x-part: [4096 x 512]
        split_mat<<<(totW + 255) / 256, 256>>>(W0, INF + HH, INF, totW, Wh, Wl, 0);
        gemm_x_bf16<<<dim3(32, 128), 256>>>(Ah, Al, Wh, Wl, b0, INF);
        init_kernel<<<128, 256>>>();
        lstm_layer<<<NCTA, 256, smem>>>(W0, INF + HH, INF, out, 0);
    }

    // ---- Layer 1 ----
    {
        int totA = 16384 * HH;                // out0: [16384 x 1024]
        split_mat<<<(totA + 255) / 256, 256>>>(nullptr, HH, HH, totA, Ah, Al, 1);
        int totW = 4096 * HH;                 // W1 x-part: [4096 x 1024]
        split_mat<<<(totW + 255) / 256, 256>>>(W1, HH + HH, HH, totW, Wh, Wl, 0);
        gemm_x_bf16<<<dim3(32, 128), 256>>>(Ah, Al, Wh, Wl, b1, HH);
        init_kernel<<<128, 256>>>();
        lstm_layer<<<NCTA, 256, smem>>>(W1, HH + HH, HH, out, 1);
    }
}

// round 4
// speedup vs baseline: 1.5382x; 1.5382x over previous
#include <cuda_runtime.h>
#include <cuda_bf16.h>
#include <math.h>
#include <stdint.h>

#define BB   32
#define SS   512
#define INF  512
#define HH   1024
#define NG   4096
#define NCTA 128

// Scratch (static device globals — allocation-free per harness rules)
__device__ float g_gxT[(size_t)SS * NG * BB];   // x-part gates, [s][n][b]
__device__ float g_out0[(size_t)BB * SS * HH];  // layer0 outputs [b][s][h]
__device__ float g_hG[2][HH * BB];              // ping-pong h, layout [k4][b][4]
__device__ unsigned g_barCnt;
__device__ unsigned g_barRel;

// bf16 hi/lo split buffers
__device__ __nv_bfloat16 g_Ah[(size_t)16384 * 1024];
__device__ __nv_bfloat16 g_Al[(size_t)16384 * 1024];
__device__ __nv_bfloat16 g_W0h[(size_t)4096 * 512];
__device__ __nv_bfloat16 g_W0l[(size_t)4096 * 512];
__device__ __nv_bfloat16 g_W1h[(size_t)4096 * 1024];
__device__ __nv_bfloat16 g_W1l[(size_t)4096 * 1024];

// ---------------------------------------------------------------------------
__global__ void init_kernel() {
    int idx = blockIdx.x * blockDim.x + threadIdx.x;
    if (idx < HH * BB) g_hG[0][idx] = 0.0f;
    if (idx == 0) { g_barCnt = 0u; g_barRel = 0u; }
}

// ---------------------------------------------------------------------------
__global__ void split_mat(const float* __restrict__ src, int srcld, int cols,
                          int total, __nv_bfloat16* __restrict__ hi,
                          __nv_bfloat16* __restrict__ lo, int use_out0)
{
    const float* s = use_out0 ? g_out0 : src;
    int idx = blockIdx.x * blockDim.x + threadIdx.x;
    if (idx >= total) return;
    int r = idx / cols, c = idx - r * cols;
    float v = s[(size_t)r * srcld + c];
    __nv_bfloat16 h = __float2bfloat16(v);
    hi[idx] = h;
    lo[idx] = __float2bfloat16(v - __bfloat162float(h));
}

// ---------------------------------------------------------------------------
__device__ __forceinline__ void mma16816(float* d, const uint32_t* a,
                                         const uint32_t* b)
{
    asm volatile(
        "mma.sync.aligned.m16n8k16.row.col.f32.bf16.bf16.f32 "
        "{%0,%1,%2,%3}, {%4,%5,%6,%7}, {%8,%9}, {%0,%1,%2,%3};\n"
        : "+f"(d[0]), "+f"(d[1]), "+f"(d[2]), "+f"(d[3])
        : "r"(a[0]), "r"(a[1]), "r"(a[2]), "r"(a[3]), "r"(b[0]), "r"(b[1]));
}

// Tensor-core x-projection GEMM, 3-term bf16 split, fp32 accumulate.
// CTA tile 128x128, 8 warps (warp tile 64x32), k-chunk 64.
// Dynamic smem: 4 arrays of 128 rows x 36 words (32 data + 4 pad) = 73728 B.
#define GX_SMEM_WORDS (4 * 128 * 36)

__global__ __launch_bounds__(256) void gemm_x_bf16(
    const __nv_bfloat16* __restrict__ Ah, const __nv_bfloat16* __restrict__ Al,
    const __nv_bfloat16* __restrict__ Bh, const __nv_bfloat16* __restrict__ Bl,
    const float* __restrict__ bias, int K)
{
    extern __shared__ uint32_t smg[];
    uint32_t* smA_h = smg;
    uint32_t* smA_l = smg + 128 * 36;
    uint32_t* smB_h = smg + 2 * 128 * 36;
    uint32_t* smB_l = smg + 3 * 128 * 36;

    const int tid  = threadIdx.x;
    const int n0   = blockIdx.x * 128;
    const int m0   = blockIdx.y * 128;
    const int wid  = tid >> 5, lane = tid & 31;
    const int wm   = (wid >> 2) * 64;
    const int wn   = (wid & 3) * 32;
    const int g    = lane >> 2, t = lane & 3;

    float acc[4][4][4];
#pragma unroll
    for (int mt = 0; mt < 4; mt++)
#pragma unroll
        for (int nt = 0; nt < 4; nt++)
#pragma unroll
            for (int i = 0; i < 4; i++) acc[mt][nt][i] = 0.0f;

    for (int k0 = 0; k0 < K; k0 += 64) {
        __syncthreads();
#pragma unroll
        for (int i = 0; i < 4; i++) {
            int q = i * 256 + tid;          // 0..1023
            int r = q >> 3, c = q & 7;      // row, uint4 col (16B = 8 bf16)
            size_t offA = (size_t)(m0 + r) * K + k0;
            size_t offB = (size_t)(n0 + r) * K + k0;
            *(uint4*)&smA_h[r * 36 + c * 4] = ((const uint4*)(Ah + offA))[c];
            *(uint4*)&smA_l[r * 36 + c * 4] = ((const uint4*)(Al + offA))[c];
            *(uint4*)&smB_h[r * 36 + c * 4] = ((const uint4*)(Bh + offB))[c];
            *(uint4*)&smB_l[r * 36 + c * 4] = ((const uint4*)(Bl + offB))[c];
        }
        __syncthreads();

#pragma unroll
        for (int kk = 0; kk < 4; kk++) {
            const int kb = kk * 8;
            uint32_t ah[4][4], al[4][4];
#pragma unroll
            for (int mt = 0; mt < 4; mt++) {
                int r0 = wm + mt * 16;
                ah[mt][0] = smA_h[(r0 + g)     * 36 + kb + t];
                ah[mt][1] = smA_h[(r0 + g + 8) * 36 + kb + t];
                ah[mt][2] = smA_h[(r0 + g)     * 36 + kb + t + 4];
                ah[mt][3] = smA_h[(r0 + g + 8) * 36 + kb + t + 4];
                al[mt][0] = smA_l[(r0 + g)     * 36 + kb + t];
                al[mt][1] = smA_l[(r0 + g + 8) * 36 + kb + t];
                al[mt][2] = smA_l[(r0 + g)     * 36 + kb + t + 4];
                al[mt][3] = smA_l[(r0 + g + 8) * 36 + kb + t + 4];
            }
#pragma unroll
            for (int nt = 0; nt < 4; nt++) {
                int c0 = wn + nt * 8;
                uint32_t bh[2], bl[2];
                bh[0] = smB_h[(c0 + g) * 36 + kb + t];
                bh[1] = smB_h[(c0 + g) * 36 + kb + t + 4];
                bl[0] = smB_l[(c0 + g) * 36 + kb + t];
                bl[1] = smB_l[(c0 + g) * 36 + kb + t + 4];
#pragma unroll
                for (int mt = 0; mt < 4; mt++) {
                    mma16816(acc[mt][nt], ah[mt], bh);
                    mma16816(acc[mt][nt], ah[mt], bl);
                    mma16816(acc[mt][nt], al[mt], bh);
                }
            }
        }
    }

    // epilogue: scatter to g_gxT[s][n][b] + bias
#pragma unroll
    for (int mt = 0; mt < 4; mt++) {
        int m1 = m0 + wm + mt * 16 + g;
        int m2 = m1 + 8;
        int b1 = m1 >> 9, s1 = m1 & 511;
        int b2 = m2 >> 9, s2 = m2 & 511;
#pragma unroll
        for (int nt = 0; nt < 4; nt++) {
            int n = n0 + wn + nt * 8 + 2 * t;
            float2 bv = *(const float2*)&bias[n];
            size_t o1 = ((size_t)s1 * NG + n) * BB + b1;
            size_t o2 = ((size_t)s2 * NG + n) * BB + b2;
            g_gxT[o1]      = acc[mt][nt][0] + bv.x;
            g_gxT[o1 + BB] = acc[mt][nt][1] + bv.y;
            g_gxT[o2]      = acc[mt][nt][2] + bv.x;
            g_gxT[o2 + BB] = acc[mt][nt][3] + bv.y;
        }
    }
}

// ---------------------------------------------------------------------------
// Persistent recurrent kernel (unchanged, proven): 128 CTAs x 256 thr,
// 1 CTA/SM; Wh slice (128 KB fp32) resident in smem for all 512 steps.
#define SMEM_FLOATS (32768 + 8192 + 8448)

__global__ __launch_bounds__(256, 1) void lstm_layer(
    const float* __restrict__ W, int ldw, int Din,
    float* __restrict__ out, int layer)
{
    extern __shared__ float sm[];
    float* Wsm  = sm;
    float* hc   = sm + 32768;
    float* part = sm + 32768 + 8192;

    const int tid = threadIdx.x;
    const int cta = blockIdx.x;
    const int j0  = cta * 8;

    for (int i = 0; i < 32; i++) {
        int q  = i * 256 + tid;
        int l  = q & 31;
        int k4 = q >> 5;
        int gate = l >> 3, jj = l & 7;
        int n = gate * 1024 + j0 + jj;
        *(float4*)&Wsm[q * 4] =
            *(const float4*)(W + (size_t)n * ldw + Din + k4 * 4);
    }

    const int g  = tid >> 5;
    const int gt = tid & 31;
    const int b0 = (gt & 7) * 4;
    const int l0 = (gt >> 3) * 8;
    const int ub = tid & 31;
    const int uj = tid >> 5;
    const int ujglob = j0 + uj;

    float c_state = 0.0f;
    float h_last  = 0.0f;
    unsigned round = 0;

    __syncthreads();

    for (int t = 0; t < SS; t++) {
        round++;
        __syncthreads();
        if (tid == 0) {
            __threadfence();
            unsigned arrived = atomicAdd(&g_barCnt, 1u) + 1u;
            if (arrived == round * NCTA) {
                atomicExch(&g_barRel, round);
            } else {
                while (atomicAdd(&g_barRel, 0u) < round) { __nanosleep(128); }
            }
            __threadfence();
        }
        __syncthreads();

        const float* hin = g_hG[t & 1];

        float acc[4][8];
#pragma unroll
        for (int bb = 0; bb < 4; bb++)
#pragma unroll
            for (int nn = 0; nn < 8; nn++) acc[bb][nn] = 0.0f;

        for (int cch = 0; cch < 4; cch++) {
#pragma unroll
            for (int i = 0; i < 8; i++) {
                int q   = i * 256 + tid;
                int b   = q & 31;
                int idx = q >> 5;
                int gg  = idx >> 3, k4i = idx & 7;
                int k4  = gg * 32 + cch * 8 + k4i;
                *(float4*)&hc[q * 4] =
                    __ldcg((const float4*)&hin[(k4 * 32 + b) * 4]);
            }
            __syncthreads();
#pragma unroll
            for (int k4i = 0; k4i < 8; k4i++) {
                int k4    = g * 32 + cch * 8 + k4i;
                int hbase = (g * 8 + k4i) * 32;
                float4 hv[4];
#pragma unroll
                for (int bb = 0; bb < 4; bb++)
                    hv[bb] = *(float4*)&hc[(hbase + b0 + bb) * 4];
#pragma unroll
                for (int nn = 0; nn < 8; nn++) {
                    float4 wv = *(float4*)&Wsm[(k4 * 32 + l0 + nn) * 4];
#pragma unroll
                    for (int bb = 0; bb < 4; bb++)
                        acc[bb][nn] += hv[bb].x * wv.x + hv[bb].y * wv.y
                                     + hv[bb].z * wv.z + hv[bb].w * wv.w;
                }
            }
            __syncthreads();
        }

#pragma unroll
        for (int nn = 0; nn < 8; nn++)
#pragma unroll
            for (int bb = 0; bb < 4; bb++)
                part[(g * 32 + l0 + nn) * 33 + b0 + bb] = acc[bb][nn];
        __syncthreads();

        {
            size_t gbase = ((size_t)t * NG + ujglob) * BB + ub;
            float pi = g_gxT[gbase];
            float pf = g_gxT[gbase + (size_t)1024 * BB];
            float pg = g_gxT[gbase + (size_t)2048 * BB];
            float po = g_gxT[gbase + (size_t)3072 * BB];
#pragma unroll
            for (int gg = 0; gg < 8; gg++) {
                pi += part[(gg * 32 +  0 + uj) * 33 + ub];
                pf += part[(gg * 32 +  8 + uj) * 33 + ub];
                pg += part[(gg * 32 + 16 + uj) * 33 + ub];
                po += part[(gg * 32 + 24 + uj) * 33 + ub];
            }
            float gi = 1.0f / (1.0f + expf(-pi));
            float gf = 1.0f / (1.0f + expf(-pf));
            float gg_ = tanhf(pg);
            float go = 1.0f / (1.0f + expf(-po));
            c_state = gf * c_state + gi * gg_;
            float h = go * tanhf(c_state);
            h_last = h;
            __stcg(&g_hG[(t + 1) & 1][((ujglob >> 2) * 32 + ub) * 4 + (ujglob & 3)], h);
            if (layer == 0)
                g_out0[((size_t)ub * SS + t) * HH + ujglob] = h;
        }
    }

    out[32768 + layer * 32768 + ub * 1024 + ujglob] = h_last;
    out[98304 + layer * 32768 + ub * 1024 + ujglob] = c_state;
    if (layer == 1) out[ub * 1024 + ujglob] = h_last;
}

// ---------------------------------------------------------------------------
extern "C" void kernel_launch(void* const* d_in, const int* in_sizes, int n_in,
                              void* d_out, int out_size)
{
    const float* x  = (const float*)d_in[0];
    const float* W0 = (const float*)d_in[1];
    const float* b0 = (const float*)d_in[2];
    const float* W1 = (const float*)d_in[3];
    const float* b1 = (const float*)d_in[4];
    float* out = (float*)d_out;

    cudaFuncSetAttribute(lstm_layer,
        cudaFuncAttributeMaxDynamicSharedMemorySize, SMEM_FLOATS * 4);
    cudaFuncSetAttribute(gemm_x_bf16,
        cudaFuncAttributeMaxDynamicSharedMemorySize, GX_SMEM_WORDS * 4);
    const int smem  = SMEM_FLOATS * 4;
    const int smemG = GX_SMEM_WORDS * 4;

    __nv_bfloat16 *Ah, *Al, *W0h, *W0l, *W1h, *W1l;
    cudaGetSymbolAddress((void**)&Ah,  g_Ah);
    cudaGetSymbolAddress((void**)&Al,  g_Al);
    cudaGetSymbolAddress((void**)&W0h, g_W0h);
    cudaGetSymbolAddress((void**)&W0l, g_W0l);
    cudaGetSymbolAddress((void**)&W1h, g_W1h);
    cudaGetSymbolAddress((void**)&W1l, g_W1l);

    // Launch order puts lstm_layer(layer 0) at index 5 so ncu -s 5 captures it.
    // [0] split W0, [1] split W1
    {
        int totW0 = 4096 * INF;
        split_mat<<<(totW0 + 255) / 256, 256>>>(W0, INF + HH, INF, totW0, W0h, W0l, 0);
        int totW1 = 4096 * HH;
        split_mat<<<(totW1 + 255) / 256, 256>>>(W1, HH + HH, HH, totW1, W1h, W1l, 0);
    }

    // ---- Layer 0: [2] split A0, [3] gemm, [4] init, [5] lstm ----
    {
        int totA = 16384 * INF;
        split_mat<<<(totA + 255) / 256, 256>>>(x, INF, INF, totA, Ah, Al, 0);
        gemm_x_bf16<<<dim3(32, 128), 256, smemG>>>(Ah, Al, W0h, W0l, b0, INF);
        init_kernel<<<128, 256>>>();
        lstm_layer<<<NCTA, 256, smem>>>(W0, INF + HH, INF, out, 0);
    }

    // ---- Layer 1: [6] split A1, [7] gemm, [8] init, [9] lstm ----
    {
        int totA = 16384 * HH;
        split_mat<<<(totA + 255) / 256, 256>>>(nullptr, HH, HH, totA, Ah, Al, 1);
        gemm_x_bf16<<<dim3(32, 128), 256, smemG>>>(Ah, Al, W1h, W1l, b1, HH);
        init_kernel<<<128, 256>>>();
        lstm_layer<<<NCTA, 256, smem>>>(W1, HH + HH, HH, out, 1);
    }
}

// round 6
// speedup vs baseline: 2.8802x; 1.8725x over previous
#include <cuda_runtime.h>
#include <cuda_bf16.h>
#include <math.h>
#include <stdint.h>

#define BB   32
#define SS   512
#define INF  512
#define HH   1024
#define NG   4096
#define NCTA 128

// Scratch (static device globals — allocation-free per harness rules)
__device__ float g_gxT[(size_t)SS * NG * BB];   // x-part gates, [s][n][b]
__device__ unsigned g_barCnt;
__device__ unsigned g_barRel;

// bf16 hi/lo split buffers. g_Ah/g_Al double as: (a) split of x / layer0-h for
// the x-projection GEMMs, (b) the recurrent h ping buffer (row = b*512 + t).
__device__ __nv_bfloat16 g_Ah[(size_t)16384 * 1024];
__device__ __nv_bfloat16 g_Al[(size_t)16384 * 1024];
__device__ __nv_bfloat16 g_W0h[(size_t)4096 * 512];
__device__ __nv_bfloat16 g_W0l[(size_t)4096 * 512];
__device__ __nv_bfloat16 g_W1h[(size_t)4096 * 1024];
__device__ __nv_bfloat16 g_W1l[(size_t)4096 * 1024];

// ---------------------------------------------------------------------------
__global__ void init_kernel() {
    if (threadIdx.x == 0 && blockIdx.x == 0) { g_barCnt = 0u; g_barRel = 0u; }
}

// ---------------------------------------------------------------------------
__global__ void split_mat(const float* __restrict__ src, int srcld, int cols,
                          int total, __nv_bfloat16* __restrict__ hi,
                          __nv_bfloat16* __restrict__ lo)
{
    int idx = blockIdx.x * blockDim.x + threadIdx.x;
    if (idx >= total) return;
    int r = idx / cols, c = idx - r * cols;
    float v = src[(size_t)r * srcld + c];
    __nv_bfloat16 h = __float2bfloat16(v);
    hi[idx] = h;
    lo[idx] = __float2bfloat16(v - __bfloat162float(h));
}

// ---------------------------------------------------------------------------
__device__ __forceinline__ void mma16816(float* d, const uint32_t* a,
                                         const uint32_t* b)
{
    asm volatile(
        "mma.sync.aligned.m16n8k16.row.col.f32.bf16.bf16.f32 "
        "{%0,%1,%2,%3}, {%4,%5,%6,%7}, {%8,%9}, {%0,%1,%2,%3};\n"
        : "+f"(d[0]), "+f"(d[1]), "+f"(d[2]), "+f"(d[3])
        : "r"(a[0]), "r"(a[1]), "r"(a[2]), "r"(a[3]), "r"(b[0]), "r"(b[1]));
}

// ---------------------------------------------------------------------------
// x-projection GEMM, 3-term bf16 split. CTA tile 128(M)x64(N), 8 warps
// (warp tile 32x32), k-chunk 64, 2 CTAs/SM.
#define GX_SMEM_WORDS (2 * 128 * 36 + 2 * 64 * 36)

__global__ __launch_bounds__(256, 2) void gemm_x_bf16(
    const __nv_bfloat16* __restrict__ Ah, const __nv_bfloat16* __restrict__ Al,
    const __nv_bfloat16* __restrict__ Bh, const __nv_bfloat16* __restrict__ Bl,
    const float* __restrict__ bias, int K)
{
    extern __shared__ uint32_t smg[];
    uint32_t* smA_h = smg;
    uint32_t* smA_l = smg + 128 * 36;
    uint32_t* smB_h = smg + 2 * 128 * 36;
    uint32_t* smB_l = smg + 2 * 128 * 36 + 64 * 36;

    const int tid  = threadIdx.x;
    const int n0   = blockIdx.x * 64;
    const int m0   = blockIdx.y * 128;
    const int wid  = tid >> 5, lane = tid & 31;
    const int wm   = (wid >> 1) * 32;
    const int wn   = (wid & 1) * 32;
    const int g    = lane >> 2, t = lane & 3;

    float acc[2][4][4];
#pragma unroll
    for (int mt = 0; mt < 2; mt++)
#pragma unroll
        for (int nt = 0; nt < 4; nt++)
#pragma unroll
            for (int i = 0; i < 4; i++) acc[mt][nt][i] = 0.0f;

    for (int k0 = 0; k0 < K; k0 += 64) {
        __syncthreads();
#pragma unroll
        for (int i = 0; i < 4; i++) {
            int q = i * 256 + tid;
            int r = q >> 3, c = q & 7;
            size_t offA = (size_t)(m0 + r) * K + k0;
            *(uint4*)&smA_h[r * 36 + c * 4] = ((const uint4*)(Ah + offA))[c];
            *(uint4*)&smA_l[r * 36 + c * 4] = ((const uint4*)(Al + offA))[c];
        }
#pragma unroll
        for (int i = 0; i < 2; i++) {
            int q = i * 256 + tid;
            int r = q >> 3, c = q & 7;
            size_t offB = (size_t)(n0 + r) * K + k0;
            *(uint4*)&smB_h[r * 36 + c * 4] = ((const uint4*)(Bh + offB))[c];
            *(uint4*)&smB_l[r * 36 + c * 4] = ((const uint4*)(Bl + offB))[c];
        }
        __syncthreads();

#pragma unroll
        for (int kk = 0; kk < 4; kk++) {
            const int kb = kk * 8;
            uint32_t ah[2][4], al[2][4];
#pragma unroll
            for (int mt = 0; mt < 2; mt++) {
                int r0 = wm + mt * 16;
                ah[mt][0] = smA_h[(r0 + g)     * 36 + kb + t];
                ah[mt][1] = smA_h[(r0 + g + 8) * 36 + kb + t];
                ah[mt][2] = smA_h[(r0 + g)     * 36 + kb + t + 4];
                ah[mt][3] = smA_h[(r0 + g + 8) * 36 + kb + t + 4];
                al[mt][0] = smA_l[(r0 + g)     * 36 + kb + t];
                al[mt][1] = smA_l[(r0 + g + 8) * 36 + kb + t];
                al[mt][2] = smA_l[(r0 + g)     * 36 + kb + t + 4];
                al[mt][3] = smA_l[(r0 + g + 8) * 36 + kb + t + 4];
            }
#pragma unroll
            for (int nt = 0; nt < 4; nt++) {
                int c0 = wn + nt * 8;
                uint32_t bh[2], bl[2];
                bh[0] = smB_h[(c0 + g) * 36 + kb + t];
                bh[1] = smB_h[(c0 + g) * 36 + kb + t + 4];
                bl[0] = smB_l[(c0 + g) * 36 + kb + t];
                bl[1] = smB_l[(c0 + g) * 36 + kb + t + 4];
#pragma unroll
                for (int mt = 0; mt < 2; mt++) {
                    mma16816(acc[mt][nt], ah[mt], bh);
                    mma16816(acc[mt][nt], ah[mt], bl);
                    mma16816(acc[mt][nt], al[mt], bh);
                }
            }
        }
    }

#pragma unroll
    for (int mt = 0; mt < 2; mt++) {
        int m1 = m0 + wm + mt * 16 + g;
        int m2 = m1 + 8;
        int b1 = m1 >> 9, s1 = m1 & 511;
        int b2 = m2 >> 9, s2 = m2 & 511;
#pragma unroll
        for (int nt = 0; nt < 4; nt++) {
            int n = n0 + wn + nt * 8 + 2 * t;
            float2 bv = *(const float2*)&bias[n];
            size_t o1 = ((size_t)s1 * NG + n) * BB + b1;
            size_t o2 = ((size_t)s2 * NG + n) * BB + b2;
            g_gxT[o1]      = acc[mt][nt][0] + bv.x;
            g_gxT[o1 + BB] = acc[mt][nt][1] + bv.y;
            g_gxT[o2]      = acc[mt][nt][2] + bv.x;
            g_gxT[o2 + BB] = acc[mt][nt][3] + bv.y;
        }
    }
}

// ---------------------------------------------------------------------------
// Persistent recurrent kernel, HMMA version. 128 CTAs x 256 thr, 1 CTA/SM.
// CTA owns 8 hidden units (32 gate rows). W slice split hi/lo bf16 in smem.
// Per step: y[b][n] = sum_k h[b][k] * W[n][k] via m16n8k16, 3-term split,
// k-split 8 warps, fp32 partial reduce in smem.
#define LS_W_L   16512
#define LS_HC_H  33024
#define LS_HC_L  37248
#define LS_PART  41472
#define LS_SMEM_BYTES (49920 * 4)

__global__ __launch_bounds__(256, 1) void lstm_layer(
    const float* __restrict__ W, int ldw, int Din,
    float* __restrict__ out, int layer)
{
    extern __shared__ uint32_t smu[];
    uint32_t* Wsh = smu;
    uint32_t* Wsl = smu + LS_W_L;
    uint32_t* Hh  = smu + LS_HC_H;
    uint32_t* Hl  = smu + LS_HC_L;
    float*    part = (float*)(smu + LS_PART);

    const int tid  = threadIdx.x;
    const int cta  = blockIdx.x;
    const int j0   = cta * 8;
    const int wid  = tid >> 5, lane = tid & 31;
    const int g    = lane >> 2, t4 = lane & 3;

    // ---- Load + split recurrent W slice once (32 rows x 1024 k) ----
    for (int i = 0; i < 64; i++) {
        int q  = i * 256 + tid;          // word idx [0, 16384)
        int l  = q >> 9;                 // row 0..31
        int wk = q & 511;                // word in row
        int gate = l >> 3, jj = l & 7;
        int n = gate * 1024 + j0 + jj;
        float2 v = *(const float2*)(W + (size_t)n * ldw + Din + wk * 2);
        __nv_bfloat16 hx = __float2bfloat16(v.x);
        __nv_bfloat16 hy = __float2bfloat16(v.y);
        __nv_bfloat16 lx = __float2bfloat16(v.x - __bfloat162float(hx));
        __nv_bfloat16 ly = __float2bfloat16(v.y - __bfloat162float(hy));
        Wsh[l * 516 + wk] = (uint32_t)__bfloat16_as_ushort(hx)
                          | ((uint32_t)__bfloat16_as_ushort(hy) << 16);
        Wsl[l * 516 + wk] = (uint32_t)__bfloat16_as_ushort(lx)
                          | ((uint32_t)__bfloat16_as_ushort(ly) << 16);
    }

    const int ub = tid & 31;     // batch
    const int uj = tid >> 5;     // hidden unit within CTA (0..7)
    const int ujglob = j0 + uj;

    float c_state = 0.0f;
    float h_last  = 0.0f;
    unsigned round = 0;

    __syncthreads();

    for (int tstep = 0; tstep < SS; tstep++) {
        // ---- grid barrier ----
        round++;
        __syncthreads();
        if (tid == 0) {
            __threadfence();
            unsigned arrived = atomicAdd(&g_barCnt, 1u) + 1u;
            if (arrived == round * NCTA) {
                atomicExch(&g_barRel, round);
            } else {
                volatile unsigned* rel = &g_barRel;
                while (*rel < round) {}
            }
            __threadfence();
        }
        __syncthreads();

        float acc[2][4][4];
#pragma unroll
        for (int mt = 0; mt < 2; mt++)
#pragma unroll
            for (int nt = 0; nt < 4; nt++)
#pragma unroll
                for (int i = 0; i < 4; i++) acc[mt][nt][i] = 0.0f;

        if (tstep > 0) {
            for (int cch = 0; cch < 4; cch++) {
                __syncthreads();
                // stage h chunk: rows b, k words [cch*128, cch*128+128)
#pragma unroll
                for (int i = 0; i < 4; i++) {
                    int q  = i * 256 + tid;      // [0, 1024)
                    int b  = q >> 5, u4 = q & 31;
                    size_t base = ((size_t)(b * 512 + tstep - 1)) * 1024
                                + cch * 256;
                    *(uint4*)&Hh[b * 132 + u4 * 4] =
                        __ldcg((const uint4*)(g_Ah + base) + u4);
                    *(uint4*)&Hl[b * 132 + u4 * 4] =
                        __ldcg((const uint4*)(g_Al + base) + u4);
                }
                __syncthreads();

                // warp wid owns ksteps {2*wid, 2*wid+1} of 16 in this chunk
#pragma unroll
                for (int s = 0; s < 2; s++) {
                    int ks = wid * 2 + s;
                    int aw = ks * 8 + t4;
                    int bw = cch * 128 + ks * 8 + t4;
                    uint32_t ah[2][4], al[2][4];
#pragma unroll
                    for (int mt = 0; mt < 2; mt++) {
                        int r = mt * 16 + g;
                        ah[mt][0] = Hh[r * 132 + aw];
                        ah[mt][1] = Hh[(r + 8) * 132 + aw];
                        ah[mt][2] = Hh[r * 132 + aw + 4];
                        ah[mt][3] = Hh[(r + 8) * 132 + aw + 4];
                        al[mt][0] = Hl[r * 132 + aw];
                        al[mt][1] = Hl[(r + 8) * 132 + aw];
                        al[mt][2] = Hl[r * 132 + aw + 4];
                        al[mt][3] = Hl[(r + 8) * 132 + aw + 4];
                    }
#pragma unroll
                    for (int nt = 0; nt < 4; nt++) {
                        int rn = nt * 8 + g;
                        uint32_t bh[2], bl[2];
                        bh[0] = Wsh[rn * 516 + bw];
                        bh[1] = Wsh[rn * 516 + bw + 4];
                        bl[0] = Wsl[rn * 516 + bw];
                        bl[1] = Wsl[rn * 516 + bw + 4];
#pragma unroll
                        for (int mt = 0; mt < 2; mt++) {
                            mma16816(acc[mt][nt], ah[mt], bh);
                            mma16816(acc[mt][nt], ah[mt], bl);
                            mma16816(acc[mt][nt], al[mt], bh);
                        }
                    }
                }
            }
            // store partials (SCALAR stores — stride 33 is odd, float2 would
            // be 4-byte-misaligned for odd rows; that was the R5 trap)
#pragma unroll
            for (int mt = 0; mt < 2; mt++) {
                int b = mt * 16 + g;
#pragma unroll
                for (int nt = 0; nt < 4; nt++) {
                    int l = nt * 8 + 2 * t4;
                    part[(wid * 32 + b) * 33 + l]     = acc[mt][nt][0];
                    part[(wid * 32 + b) * 33 + l + 1] = acc[mt][nt][1];
                    part[(wid * 32 + b + 8) * 33 + l]     = acc[mt][nt][2];
                    part[(wid * 32 + b + 8) * 33 + l + 1] = acc[mt][nt][3];
                }
            }
            __syncthreads();
        }

        // ---- reduce + activations + state update ----
        {
            size_t gbase = ((size_t)tstep * NG + ujglob) * BB + ub;
            float pi = g_gxT[gbase];
            float pf = g_gxT[gbase + (size_t)1024 * BB];
            float pg = g_gxT[gbase + (size_t)2048 * BB];
            float po = g_gxT[gbase + (size_t)3072 * BB];
            if (tstep > 0) {
#pragma unroll
                for (int w = 0; w < 8; w++) {
                    int base = (w * 32 + ub) * 33 + uj;
                    pi += part[base];
                    pf += part[base + 8];
                    pg += part[base + 16];
                    po += part[base + 24];
                }
            }
            float gi = 1.0f / (1.0f + expf(-pi));
            float gf = 1.0f / (1.0f + expf(-pf));
            float gg = tanhf(pg);
            float go = 1.0f / (1.0f + expf(-po));
            c_state = gf * c_state + gi * gg;
            float h = go * tanhf(c_state);
            h_last = h;
            __nv_bfloat16 hh = __float2bfloat16(h);
            __nv_bfloat16 hl = __float2bfloat16(h - __bfloat162float(hh));
            size_t hrow = ((size_t)(ub * 512 + tstep)) * 1024 + ujglob;
            g_Ah[hrow] = hh;
            g_Al[hrow] = hl;
        }
    }

    out[32768 + layer * 32768 + ub * 1024 + ujglob] = h_last;
    out[98304 + layer * 32768 + ub * 1024 + ujglob] = c_state;
    if (layer == 1) out[ub * 1024 + ujglob] = h_last;
}

// ---------------------------------------------------------------------------
extern "C" void kernel_launch(void* const* d_in, const int* in_sizes, int n_in,
                              void* d_out, int out_size)
{
    const float* x  = (const float*)d_in[0];
    const float* W0 = (const float*)d_in[1];
    const float* b0 = (const float*)d_in[2];
    const float* W1 = (const float*)d_in[3];
    const float* b1 = (const float*)d_in[4];
    float* out = (float*)d_out;

    cudaFuncSetAttribute(lstm_layer,
        cudaFuncAttributeMaxDynamicSharedMemorySize, LS_SMEM_BYTES);
    cudaFuncSetAttribute(gemm_x_bf16,
        cudaFuncAttributeMaxDynamicSharedMemorySize, GX_SMEM_WORDS * 4);

    __nv_bfloat16 *Ah, *Al, *W0h, *W0l, *W1h, *W1l;
    cudaGetSymbolAddress((void**)&Ah,  g_Ah);
    cudaGetSymbolAddress((void**)&Al,  g_Al);
    cudaGetSymbolAddress((void**)&W0h, g_W0h);
    cudaGetSymbolAddress((void**)&W0l, g_W0l);
    cudaGetSymbolAddress((void**)&W1h, g_W1h);
    cudaGetSymbolAddress((void**)&W1l, g_W1l);

    // [0] split W0 x-part, [1] split W1 x-part, [2] split x
    {
        int totW0 = 4096 * INF;
        split_mat<<<(totW0 + 255) / 256, 256>>>(W0, INF + HH, INF, totW0, W0h, W0l);
        int totW1 = 4096 * HH;
        split_mat<<<(totW1 + 255) / 256, 256>>>(W1, HH + HH, HH, totW1, W1h, W1l);
        int totA = 16384 * INF;
        split_mat<<<(totA + 255) / 256, 256>>>(x, INF, INF, totA, Ah, Al);
    }

    // ---- Layer 0: [3] gemm, [4] init, [5] lstm (ncu -s 5 lands here) ----
    gemm_x_bf16<<<dim3(64, 128), 256, GX_SMEM_WORDS * 4>>>(Ah, Al, W0h, W0l, b0, INF);
    init_kernel<<<1, 32>>>();
    lstm_layer<<<NCTA, 256, LS_SMEM_BYTES>>>(W0, INF + HH, INF, out, 0);

    // ---- Layer 1: [6] gemm (A = layer0 h, written by lstm), [7] init, [8] lstm
    gemm_x_bf16<<<dim3(64, 128), 256, GX_SMEM_WORDS * 4>>>(Ah, Al, W1h, W1l, b1, HH);
    init_kernel<<<1, 32>>>();
    lstm_layer<<<NCTA, 256, LS_SMEM_BYTES>>>(W1, HH + HH, HH, out, 1);
}